// round 3
// baseline (speedup 1.0000x reference)
#include <cuda_runtime.h>
#include <math.h>

#define BB   4
#define HWD  16384
#define SPPX 3
#define CCH  64
#define NG   (BB*HWD*SPPX)      /* 196608 gaussians */
#define GPB  256                /* gaussians per block */

/* output layout (floats): means|cov|sh|opa|feat|scales|rot */
#define OFF_MEANS ((size_t)0)
#define OFF_COV   ((size_t)3*NG)
#define OFF_SH    ((size_t)12*NG)
#define OFF_OPA   ((size_t)87*NG)
#define OFF_FEAT  ((size_t)88*NG)
#define OFF_SCL   ((size_t)152*NG)
#define OFF_ROT   ((size_t)155*NG)

static __device__ const int d_LOFF[5]   = {0,1,10,35,84};
static __device__ const int d_GENOFF[5] = {0,3,30,105,252};

__device__ double g_SO3d[495];     /* generators, per l: [a(3)][n*n] doubles */
__device__ float  g_D[BB*165];     /* Wigner D per batch, concat l=0..4     */
__device__ float  g_cb[BB*24];     /* per-batch consts: R(9) o(3) Kinv(9) mult(1) */

/* ------------------------------------------------------------------ */
/* Kernel 1: build SO(3) generators exactly as reference (complex Q^H X Q) */
__global__ void setup_gen_kernel() {
    const int l = blockIdx.x;
    const int n = 2*l+1, n2 = n*n;
    const int lane = threadIdx.x;
    __shared__ double Qre[81],Qim[81],Xre[81],Xim[81],Tre[81],Tim[81];

    for (int i=lane;i<n2;i+=32){ Qre[i]=0.0; Qim[i]=0.0; }
    __syncwarp();
    if (lane==0){
        const double is2 = 0.70710678118654752440;
        for (int m=-l;m<0;m++){
            Qre[(l+m)*n+(l-m)] = is2;       /* q[l+m, l+|m|] = 1/sqrt2      */
            Qim[(l+m)*n+(l+m)] = -is2;      /* q[l+m, l-|m|] = -i/sqrt2     */
        }
        Qre[l*n+l] = 1.0;
        for (int m=1;m<=l;m++){
            double sg = (m&1)? -1.0 : 1.0;
            Qre[(l+m)*n+(l+m)] = sg*is2;    /* (-1)^m/sqrt2  */
            Qim[(l+m)*n+(l-m)] = sg*is2;    /* i(-1)^m/sqrt2 */
        }
    }
    __syncwarp();
    { /* multiply by (-i)^l */
        double cr,ci;
        switch (l&3){
            case 0: cr=1;  ci=0;  break;
            case 1: cr=0;  ci=-1; break;
            case 2: cr=-1; ci=0;  break;
            default:cr=0;  ci=1;  break;
        }
        for (int i=lane;i<n2;i+=32){
            double re=Qre[i], im=Qim[i];
            Qre[i]=re*cr-im*ci; Qim[i]=re*ci+im*cr;
        }
    }
    __syncwarp();

    for (int a=0;a<3;a++){
        for (int i=lane;i<n2;i+=32){ Xre[i]=0.0; Xim[i]=0.0; }
        __syncwarp();
        if (lane==0){
            double jj=(double)l;
            if (a==1){
                for (int i=0;i<n;i++) Xim[i*n+i] = (double)(-l+i);
            } else {
                for (int i=0;i<n-1;i++){
                    double m = -jj + (double)i;
                    double sq = sqrt(jj*(jj+1.0) - m*(m+1.0));
                    if (a==0){ Xre[(i+1)*n+i] = -0.5*sq; Xre[i*n+(i+1)] = 0.5*sq; }
                    else     { Xim[(i+1)*n+i] =  0.5*sq; Xim[i*n+(i+1)] = 0.5*sq; }
                }
            }
        }
        __syncwarp();
        /* T = X @ Q */
        for (int idx=lane; idx<n2; idx+=32){
            int r=idx/n, c=idx-r*n;
            double sre=0, sim=0;
            for (int k=0;k<n;k++){
                double xr=Xre[r*n+k], xi=Xim[r*n+k];
                double qr=Qre[k*n+c], qi=Qim[k*n+c];
                sre += xr*qr - xi*qi;
                sim += xr*qi + xi*qr;
            }
            Tre[idx]=sre; Tim[idx]=sim;
        }
        __syncwarp();
        /* G = Re(Q^H @ T) */
        for (int idx=lane; idx<n2; idx+=32){
            int r=idx/n, c=idx-r*n;
            double s=0;
            for (int k=0;k<n;k++)
                s += Qre[k*n+r]*Tre[k*n+c] + Qim[k*n+r]*Tim[k*n+c];
            g_SO3d[d_GENOFF[l] + a*n2 + idx] = s;
        }
        __syncwarp();
    }
}

/* ------------------------------------------------------------------ */
/* warp-parallel n x n double matmul + expm (scaling & squaring)      */
__device__ __forceinline__ void wmm(const double* A, const double* B, double* C,
                                    int n, int lane){
    for (int idx=lane; idx<n*n; idx+=32){
        int r=idx/n, c=idx-r*n;
        double s=0.0;
        for (int k=0;k<n;k++) s += A[r*n+k]*B[k*n+c];
        C[idx]=s;
    }
}

__device__ void wexpm(double theta, const double* G, int n, int lane,
                      double* M, double* P, double* T){
    const int n2=n*n;
    for (int i=lane;i<n2;i+=32) M[i]=theta*G[i];
    __syncwarp();
    int s=0;
    if (lane==0){
        double nm=0;
        for (int r=0;r<n;r++){
            double rs=0;
            for (int c=0;c<n;c++) rs += fabs(M[r*n+c]);
            nm = fmax(nm, rs);
        }
        while (nm > 0.25){ nm*=0.5; s++; }
    }
    s = __shfl_sync(0xffffffffu, s, 0);
    double scl = ldexp(1.0, -s);
    for (int i=lane;i<n2;i+=32) M[i]*=scl;
    __syncwarp();
    for (int i=lane;i<n2;i+=32) P[i] = ((i/n)==(i%n)) ? 1.0 : 0.0;
    __syncwarp();
    for (int k=16;k>=1;k--){
        wmm(M,P,T,n,lane); __syncwarp();
        double ik = 1.0/(double)k;
        for (int i=lane;i<n2;i+=32)
            P[i] = T[i]*ik + (((i/n)==(i%n)) ? 1.0 : 0.0);
        __syncwarp();
    }
    for (int it=0; it<s; it++){
        wmm(P,P,T,n,lane); __syncwarp();
        for (int i=lane;i<n2;i+=32) P[i]=T[i];
        __syncwarp();
    }
}

__device__ __forceinline__ int read_dim(const void* p, int defv){
    if (!p) return defv;
    int iv = *(const int*)p;
    if (iv>=1 && iv<=(1<<20)) return iv;
    float fv = *(const float*)p;
    if (fv>=1.0f && fv<=1048576.0f) return (int)(fv+0.5f);
    return defv;
}

/* Kernel 2: per (batch,l) Wigner D + per-batch constants. grid=20, block=32 */
__global__ void setup_D_kernel(const float* __restrict__ ext,
                               const float* __restrict__ intr,
                               const void* ph, const void* pw){
    const int b = blockIdx.x/5, l = blockIdx.x%5;
    const int n = 2*l+1;
    const int lane = threadIdx.x;
    __shared__ double M[81],P[81],T[81],E1[81],E0[81],E2[81];

    double al=0, be=0, ga=0;
    if (lane==0){
        double R[3][3];
        for (int r=0;r<3;r++) for (int c=0;c<3;c++) R[r][c] = (double)ext[b*16+r*4+c];
        double x0=R[0][1], x1=R[1][1], x2=R[2][1];
        double inv = 1.0/sqrt(x0*x0+x1*x1+x2*x2);
        x0*=inv; x1*=inv; x2*=inv;
        be = acos(fmin(1.0, fmax(-1.0, x1)));
        al = atan2(x0, x2);
        double ca=cos(al), sa=sin(al);
        double Rp00 = ca*R[0][0] - sa*R[2][0];
        double Rp02 = ca*R[0][2] - sa*R[2][2];
        ga = atan2(Rp02, Rp00);
    }
    al = __shfl_sync(0xffffffffu, al, 0);
    be = __shfl_sync(0xffffffffu, be, 0);
    ga = __shfl_sync(0xffffffffu, ga, 0);

    const double* Xx = g_SO3d + d_GENOFF[l];        /* a=0 (about x) */
    const double* Xy = Xx + n*n;                    /* a=1 (about y) */

    const int n2=n*n;
    wexpm(al, Xy, n, lane, M,P,T);
    for (int i=lane;i<n2;i+=32) E1[i]=P[i];
    __syncwarp();
    wexpm(-be, Xx, n, lane, M,P,T);                 /* wigner_D(l, a, -b, g) */
    for (int i=lane;i<n2;i+=32) E0[i]=P[i];
    __syncwarp();
    wexpm(ga, Xy, n, lane, M,P,T);
    for (int i=lane;i<n2;i+=32) E2[i]=P[i];
    __syncwarp();
    wmm(E0,E2,T,n,lane); __syncwarp();
    wmm(E1,T,M,n,lane);  __syncwarp();
    for (int i=lane;i<n2;i+=32)
        g_D[b*165 + d_LOFF[l] + i] = (float)M[i];

    if (l==0 && lane==0){
        double K[3][3];
        for (int r=0;r<3;r++) for (int c=0;c<3;c++) K[r][c]=(double)intr[b*9+r*3+c];
        double det = K[0][0]*(K[1][1]*K[2][2]-K[1][2]*K[2][1])
                   - K[0][1]*(K[1][0]*K[2][2]-K[1][2]*K[2][0])
                   + K[0][2]*(K[1][0]*K[2][1]-K[1][1]*K[2][0]);
        double id = 1.0/det;
        double Ki[3][3];
        Ki[0][0]=(K[1][1]*K[2][2]-K[1][2]*K[2][1])*id;
        Ki[0][1]=(K[0][2]*K[2][1]-K[0][1]*K[2][2])*id;
        Ki[0][2]=(K[0][1]*K[1][2]-K[0][2]*K[1][1])*id;
        Ki[1][0]=(K[1][2]*K[2][0]-K[1][0]*K[2][2])*id;
        Ki[1][1]=(K[0][0]*K[2][2]-K[0][2]*K[2][0])*id;
        Ki[1][2]=(K[0][2]*K[1][0]-K[0][0]*K[1][2])*id;
        Ki[2][0]=(K[1][0]*K[2][1]-K[1][1]*K[2][0])*id;
        Ki[2][1]=(K[0][1]*K[2][0]-K[0][0]*K[2][1])*id;
        Ki[2][2]=(K[0][0]*K[1][1]-K[0][1]*K[1][0])*id;

        int Hh = read_dim(ph, 128);
        int Ww = read_dim(pw, 128);
        double psx = 1.0/(double)Ww, psy = 1.0/(double)Hh;
        double d2  = K[0][0]*K[1][1]-K[0][1]*K[1][0];
        double v0  = ( K[1][1]*psx - K[0][1]*psy)/d2;
        double v1  = (-K[1][0]*psx + K[0][0]*psy)/d2;
        double mult = 0.1*(v0+v1);

        float* cb = g_cb + b*24;
        for (int r=0;r<3;r++) for (int c=0;c<3;c++) cb[r*3+c]=(float)ext[b*16+r*4+c];
        for (int r=0;r<3;r++) cb[9+r]=(float)ext[b*16+r*4+3];
        for (int r=0;r<3;r++) for (int c=0;c<3;c++) cb[12+r*3+c]=(float)Ki[r][c];
        cb[21]=(float)mult;
    }
}

/* ------------------------------------------------------------------ */
/* Kernel 3: main per-gaussian kernel, fully smem-staged I/O          */
__global__ void __launch_bounds__(GPB)
gauss_kernel(const float* __restrict__ coords, const float* __restrict__ depths,
             const float* __restrict__ opac,   const float* __restrict__ raw,
             float* __restrict__ out){
    extern __shared__ float sm[];
    float* s_in   = sm;                    /* GPB*83 (padded stride 83) */
    float* s_sh   = s_in   + GPB*83;       /* GPB*75 */
    float* s_mean = s_sh   + GPB*75;       /* GPB*3  */
    float* s_cov  = s_mean + GPB*3;        /* GPB*9  */
    float* s_scl  = s_cov  + GPB*9;        /* GPB*3  */
    float* s_rot  = s_scl  + GPB*3;        /* GPB*5 (padded stride 5) */
    float* s_D    = s_rot  + GPB*5;        /* 165 */
    float* s_cb   = s_D    + 165;          /* 24  */

    const int tid = threadIdx.x;
    const int g0  = blockIdx.x*GPB;
    const int b   = g0/(HWD*SPPX);

    if (tid < 165) s_D[tid] = g_D[b*165+tid];
    if (tid < 24)  s_cb[tid] = g_cb[b*24+tid];

    /* stage raw_gaussians: coalesced float4 loads, scatter to padded rows */
    {
        const float4* src = reinterpret_cast<const float4*>(raw + (size_t)g0*82);
        #pragma unroll 4
        for (int i=tid; i<GPB*82/4; i+=GPB){
            float4 v = src[i];
            int lin = i*4;
            float vv[4] = {v.x, v.y, v.z, v.w};
            #pragma unroll
            for (int w=0; w<4; w++){
                int t = (lin+w)/82;
                int j = (lin+w) - t*82;
                s_in[t*83 + j] = vv[w];
            }
        }
    }
    __syncthreads();

    const int g = g0 + tid;
    const float* in = s_in + tid*83;
    const float  depth = depths[g];
    const float2 uv = reinterpret_cast<const float2*>(coords)[g];
    out[OFF_OPA + g] = opac[g];                       /* already coalesced */

    /* scales */
    const float mult = s_cb[21];
    float sc[3];
    #pragma unroll
    for (int i=0;i<3;i++){
        float x = in[i];
        float sig = 1.0f/(1.0f+expf(-x));
        sc[i] = (0.5f + 14.5f*sig) * depth * mult;
    }
    /* quaternion -> rotation */
    float q0=in[3], q1=in[4], q2=in[5], q3=in[6];
    float nq = sqrtf(q0*q0+q1*q1+q2*q2+q3*q3);
    float invq = 1.0f/(nq + 1e-8f);
    q0*=invq; q1*=invq; q2*=invq; q3*=invq;
    float ss = 2.0f/(q0*q0+q1*q1+q2*q2+q3*q3);
    const float r=q0, ii=q1, jj=q2, kk=q3;
    float R00=1.f-ss*(jj*jj+kk*kk), R01=ss*(ii*jj-kk*r), R02=ss*(ii*kk+jj*r);
    float R10=ss*(ii*jj+kk*r), R11=1.f-ss*(ii*ii+kk*kk), R12=ss*(jj*kk-ii*r);
    float R20=ss*(ii*kk-jj*r), R21=ss*(jj*kk+ii*r), R22=1.f-ss*(ii*ii+jj*jj);
    float v0=sc[0]*sc[0], v1=sc[1]*sc[1], v2=sc[2]*sc[2];

    float* cv = s_cov + tid*9;
    float c00=R00*R00*v0+R01*R01*v1+R02*R02*v2;
    float c01=R00*R10*v0+R01*R11*v1+R02*R12*v2;
    float c02=R00*R20*v0+R01*R21*v1+R02*R22*v2;
    float c11=R10*R10*v0+R11*R11*v1+R12*R12*v2;
    float c12=R10*R20*v0+R11*R21*v1+R12*R22*v2;
    float c22=R20*R20*v0+R21*R21*v1+R22*R22*v2;
    cv[0]=c00; cv[1]=c01; cv[2]=c02;
    cv[3]=c01; cv[4]=c11; cv[5]=c12;
    cv[6]=c02; cv[7]=c12; cv[8]=c22;

    /* dirs -> means */
    {
        float dx = s_cb[12]*uv.x + s_cb[13]*uv.y + s_cb[14];
        float dy = s_cb[15]*uv.x + s_cb[16]*uv.y + s_cb[17];
        float dz = s_cb[18]*uv.x + s_cb[19]*uv.y + s_cb[20];
        float dn = 1.0f/sqrtf(dx*dx+dy*dy+dz*dz);
        dx*=dn; dy*=dn; dz*=dn;
        float wx = s_cb[0]*dx + s_cb[1]*dy + s_cb[2]*dz;
        float wy = s_cb[3]*dx + s_cb[4]*dy + s_cb[5]*dz;
        float wz = s_cb[6]*dx + s_cb[7]*dy + s_cb[8]*dz;
        float* mn = s_mean + tid*3;
        mn[0] = s_cb[9]  + wx*depth;
        mn[1] = s_cb[10] + wy*depth;
        mn[2] = s_cb[11] + wz*depth;
    }
    { float* sl = s_scl + tid*3; sl[0]=sc[0]; sl[1]=sc[1]; sl[2]=sc[2]; }
    { float* rt = s_rot + tid*5; rt[0]=q0; rt[1]=q1; rt[2]=q2; rt[3]=q3; }

    /* SH rotation: out_i = sum_j D_l[i][j] * (mask_l * sh_j) */
    {
        const int   LOFFc[5] = {0,1,10,35,84};
        const float MSK[5]   = {1.0f, 0.025f, 0.00625f, 0.0015625f, 0.000390625f};
        #pragma unroll
        for (int ch=0; ch<3; ch++){
            const float* shin = in + 7 + ch*25;
            float* sho = s_sh + tid*75 + ch*25;
            sho[0] = s_D[0]*shin[0];
            #pragma unroll
            for (int l=1;l<5;l++){
                const int n = 2*l+1, off = l*l;
                const float* D = s_D + LOFFc[l];
                float t[9];
                #pragma unroll
                for (int j=0;j<n;j++) t[j] = shin[off+j]*MSK[l];
                #pragma unroll
                for (int i=0;i<n;i++){
                    float s = 0.f;
                    #pragma unroll
                    for (int j=0;j<n;j++) s += D[i*n+j]*t[j];
                    sho[off+i] = s;
                }
            }
        }
    }
    __syncthreads();

    /* coalesced float4 flush */
    {
        const float4* s4; float4* d4;
        s4 = (const float4*)s_sh;   d4 = (float4*)(out + OFF_SH  + (size_t)g0*75);
        #pragma unroll 4
        for (int i=tid; i<GPB*75/4; i+=GPB) d4[i]=s4[i];
        s4 = (const float4*)s_mean; d4 = (float4*)(out + OFF_MEANS + (size_t)g0*3);
        for (int i=tid; i<GPB*3/4;  i+=GPB) d4[i]=s4[i];
        s4 = (const float4*)s_cov;  d4 = (float4*)(out + OFF_COV + (size_t)g0*9);
        #pragma unroll 2
        for (int i=tid; i<GPB*9/4;  i+=GPB) d4[i]=s4[i];
        s4 = (const float4*)s_scl;  d4 = (float4*)(out + OFF_SCL + (size_t)g0*3);
        for (int i=tid; i<GPB*3/4;  i+=GPB) d4[i]=s4[i];
        for (int i=tid; i<GPB*4;    i+=GPB){
            int gg=i>>2, j=i&3;
            out[OFF_ROT + (size_t)g0*4 + i] = s_rot[gg*5+j];
        }
    }
}

/* ------------------------------------------------------------------ */
/* Kernel 4: features = transpose(grd_feat) broadcast over SPP        */
__global__ void feat_kernel(const float* __restrict__ gf, float* __restrict__ out){
    __shared__ float tile[64][33];
    const int b   = blockIdx.y;
    const int hw0 = blockIdx.x*32;
    const int tx  = threadIdx.x;       /* 0..31 */
    const int ty  = threadIdx.y;       /* 0..7  */

    const float* src = gf + (size_t)b*CCH*HWD + hw0;
    #pragma unroll
    for (int c=ty; c<64; c+=8) tile[c][tx] = src[(size_t)c*HWD + tx];
    __syncthreads();

    #pragma unroll
    for (int k=0;k<4;k++){
        int hwl = ty + 8*k;
        size_t gbase = ((size_t)(b*HWD + hw0 + hwl))*SPPX;
        float a = tile[tx][hwl];
        float bb2 = tile[tx+32][hwl];
        #pragma unroll
        for (int spp=0; spp<SPPX; spp++){
            float* o = out + OFF_FEAT + (gbase+spp)*64;
            o[tx]    = a;
            o[tx+32] = bb2;
        }
    }
}

/* ------------------------------------------------------------------ */
extern "C" void kernel_launch(void* const* d_in, const int* in_sizes, int n_in,
                              void* d_out, int out_size){
    const float* ext    = (const float*)d_in[0];
    const float* intr   = (const float*)d_in[1];
    const float* coords = (const float*)d_in[2];
    const float* depths = (const float*)d_in[3];
    const float* opac   = (const float*)d_in[4];
    const float* raw    = (const float*)d_in[5];
    const float* gf     = (const float*)d_in[6];
    const void*  ph     = (n_in > 7) ? d_in[7] : nullptr;
    const void*  pw     = (n_in > 8) ? d_in[8] : nullptr;
    float* out = (float*)d_out;

    setup_gen_kernel<<<5, 32>>>();
    setup_D_kernel<<<20, 32>>>(ext, intr, ph, pw);

    size_t smem = (size_t)(GPB*83 + GPB*75 + GPB*3 + GPB*9 + GPB*3 + GPB*5 + 165 + 24)*sizeof(float);
    cudaFuncSetAttribute(gauss_kernel, cudaFuncAttributeMaxDynamicSharedMemorySize, (int)smem);
    gauss_kernel<<<NG/GPB, GPB, smem>>>(coords, depths, opac, raw, out);

    feat_kernel<<<dim3(HWD/32, BB), dim3(32,8)>>>(gf, out);
}

// round 5
// speedup vs baseline: 1.6808x; 1.6808x over previous
#include <cuda_runtime.h>
#include <math.h>

#define BB   4
#define HWD  16384
#define SPPX 3
#define CCH  64
#define NG   (BB*HWD*SPPX)      /* 196608 gaussians */
#define GPB  128                /* gaussians per block */

/* output layout (floats): means|cov|sh|opa|feat|scales|rot */
#define OFF_MEANS ((size_t)0)
#define OFF_COV   ((size_t)3*NG)
#define OFF_SH    ((size_t)12*NG)
#define OFF_OPA   ((size_t)87*NG)
#define OFF_FEAT  ((size_t)88*NG)
#define OFF_SCL   ((size_t)152*NG)
#define OFF_ROT   ((size_t)155*NG)

static __device__ const int d_LOFF[5]   = {0,1,10,35,84};
static __device__ const int d_GENOFF[5] = {0,3,30,105,252};

__device__ double g_SO3d[495];       /* generators, per l: [a(3)][n*n] doubles */
__device__ double g_E[BB*5*3*81];    /* per (b,l,e) matrix exponentials        */
__device__ float  g_D[BB*165];       /* Wigner D per batch, concat l=0..4      */
__device__ float  g_cb[BB*24];       /* per-batch consts: R(9) o(3) Kinv(9) mult */

/* ------------------------------------------------------------------ */
/* Kernel 1: build SO(3) generators exactly as reference (complex Q^H X Q) */
__global__ void setup_gen_kernel() {
    const int l = blockIdx.x;
    const int n = 2*l+1, n2 = n*n;
    const int lane = threadIdx.x;
    __shared__ double Qre[81],Qim[81],Xre[81],Xim[81],Tre[81],Tim[81];

    for (int i=lane;i<n2;i+=32){ Qre[i]=0.0; Qim[i]=0.0; }
    __syncwarp();
    if (lane==0){
        const double is2 = 0.70710678118654752440;
        for (int m=-l;m<0;m++){
            Qre[(l+m)*n+(l-m)] = is2;
            Qim[(l+m)*n+(l+m)] = -is2;
        }
        Qre[l*n+l] = 1.0;
        for (int m=1;m<=l;m++){
            double sg = (m&1)? -1.0 : 1.0;
            Qre[(l+m)*n+(l+m)] = sg*is2;
            Qim[(l+m)*n+(l-m)] = sg*is2;
        }
    }
    __syncwarp();
    { /* multiply by (-i)^l */
        double cr,ci;
        switch (l&3){
            case 0: cr=1;  ci=0;  break;
            case 1: cr=0;  ci=-1; break;
            case 2: cr=-1; ci=0;  break;
            default:cr=0;  ci=1;  break;
        }
        for (int i=lane;i<n2;i+=32){
            double re=Qre[i], im=Qim[i];
            Qre[i]=re*cr-im*ci; Qim[i]=re*ci+im*cr;
        }
    }
    __syncwarp();

    for (int a=0;a<3;a++){
        for (int i=lane;i<n2;i+=32){ Xre[i]=0.0; Xim[i]=0.0; }
        __syncwarp();
        if (lane==0){
            double jj=(double)l;
            if (a==1){
                for (int i=0;i<n;i++) Xim[i*n+i] = (double)(-l+i);
            } else {
                for (int i=0;i<n-1;i++){
                    double m = -jj + (double)i;
                    double sq = sqrt(jj*(jj+1.0) - m*(m+1.0));
                    if (a==0){ Xre[(i+1)*n+i] = -0.5*sq; Xre[i*n+(i+1)] = 0.5*sq; }
                    else     { Xim[(i+1)*n+i] =  0.5*sq; Xim[i*n+(i+1)] = 0.5*sq; }
                }
            }
        }
        __syncwarp();
        for (int idx=lane; idx<n2; idx+=32){
            int r=idx/n, c=idx-r*n;
            double sre=0, sim=0;
            for (int k=0;k<n;k++){
                double xr=Xre[r*n+k], xi=Xim[r*n+k];
                double qr=Qre[k*n+c], qi=Qim[k*n+c];
                sre += xr*qr - xi*qi;
                sim += xr*qi + xi*qr;
            }
            Tre[idx]=sre; Tim[idx]=sim;
        }
        __syncwarp();
        for (int idx=lane; idx<n2; idx+=32){
            int r=idx/n, c=idx-r*n;
            double s=0;
            for (int k=0;k<n;k++)
                s += Qre[k*n+r]*Tre[k*n+c] + Qim[k*n+r]*Tim[k*n+c];
            g_SO3d[d_GENOFF[l] + a*n2 + idx] = s;
        }
        __syncwarp();
    }
}

/* ------------------------------------------------------------------ */
__device__ __forceinline__ void wmm(const double* A, const double* B, double* C,
                                    int n, int lane){
    for (int idx=lane; idx<n*n; idx+=32){
        int r=idx/n, c=idx-r*n;
        double s=0.0;
        for (int k=0;k<n;k++) s += A[r*n+k]*B[k*n+c];
        C[idx]=s;
    }
}

__device__ void wexpm(double theta, const double* G, int n, int lane,
                      double* M, double* P, double* T){
    const int n2=n*n;
    for (int i=lane;i<n2;i+=32) M[i]=theta*G[i];
    __syncwarp();
    int s=0;
    if (lane==0){
        double nm=0;
        for (int r=0;r<n;r++){
            double rs=0;
            for (int c=0;c<n;c++) rs += fabs(M[r*n+c]);
            nm = fmax(nm, rs);
        }
        while (nm > 1.0){ nm*=0.5; s++; }
    }
    s = __shfl_sync(0xffffffffu, s, 0);
    double scl = ldexp(1.0, -s);
    for (int i=lane;i<n2;i+=32) M[i]*=scl;
    __syncwarp();
    for (int i=lane;i<n2;i+=32) P[i] = ((i/n)==(i%n)) ? 1.0 : 0.0;
    __syncwarp();
    for (int k=13;k>=1;k--){
        wmm(M,P,T,n,lane); __syncwarp();
        double ik = 1.0/(double)k;
        for (int i=lane;i<n2;i+=32)
            P[i] = T[i]*ik + (((i/n)==(i%n)) ? 1.0 : 0.0);
        __syncwarp();
    }
    for (int it=0; it<s; it++){
        wmm(P,P,T,n,lane); __syncwarp();
        for (int i=lane;i<n2;i+=32) P[i]=T[i];
        __syncwarp();
    }
}

__device__ __forceinline__ void get_angles(const float* __restrict__ ext, int b,
                                           double& al, double& be, double& ga){
    double R[3][3];
    for (int r=0;r<3;r++) for (int c=0;c<3;c++) R[r][c] = (double)ext[b*16+r*4+c];
    double x0=R[0][1], x1=R[1][1], x2=R[2][1];
    double inv = 1.0/sqrt(x0*x0+x1*x1+x2*x2);
    x0*=inv; x1*=inv; x2*=inv;
    be = acos(fmin(1.0, fmax(-1.0, x1)));
    al = atan2(x0, x2);
    double ca=cos(al), sa=sin(al);
    double Rp00 = ca*R[0][0] - sa*R[2][0];
    double Rp02 = ca*R[0][2] - sa*R[2][2];
    ga = atan2(Rp02, Rp00);
}

/* Kernel 2: per (b,l,e) matrix exponential. grid = BB*5*3, block = 32 */
__global__ void setup_exp_kernel(const float* __restrict__ ext){
    const int e = blockIdx.x % 3;
    const int l = (blockIdx.x/3) % 5;
    const int b = blockIdx.x/15;
    const int n = 2*l+1;
    const int lane = threadIdx.x;
    __shared__ double M[81],P[81],T[81];

    double al=0, be=0, ga=0;
    if (lane==0) get_angles(ext, b, al, be, ga);
    al = __shfl_sync(0xffffffffu, al, 0);
    be = __shfl_sync(0xffffffffu, be, 0);
    ga = __shfl_sync(0xffffffffu, ga, 0);

    const double* Xx = g_SO3d + d_GENOFF[l];   /* a=0 */
    const double* Xy = Xx + n*n;               /* a=1 */

    double theta; const double* G;
    if      (e==0){ theta = al;  G = Xy; }
    else if (e==1){ theta = -be; G = Xx; }
    else          { theta = ga;  G = Xy; }

    wexpm(theta, G, n, lane, M,P,T);
    double* dst = g_E + ((b*5+l)*3+e)*81;
    for (int i=lane;i<n*n;i+=32) dst[i]=P[i];
}

__device__ __forceinline__ int read_dim(const void* p, int defv){
    if (!p) return defv;
    int iv = *(const int*)p;
    if (iv>=1 && iv<=(1<<20)) return iv;
    float fv = *(const float*)p;
    if (fv>=1.0f && fv<=1048576.0f) return (int)(fv+0.5f);
    return defv;
}

/* Kernel 3: combine D = E0 @ E1 @ E2, plus per-batch constants. grid=20 */
__global__ void setup_combine_kernel(const float* __restrict__ ext,
                                     const float* __restrict__ intr,
                                     const void* ph, const void* pw){
    const int b = blockIdx.x/5, l = blockIdx.x%5;
    const int n = 2*l+1, n2 = n*n;
    const int lane = threadIdx.x;
    __shared__ double E0[81],E1[81],E2[81],T[81],M[81];

    const double* src = g_E + ((b*5+l)*3)*81;
    for (int i=lane;i<n2;i+=32){ E0[i]=src[i]; E1[i]=src[81+i]; E2[i]=src[162+i]; }
    __syncwarp();
    wmm(E1,E2,T,n,lane); __syncwarp();
    wmm(E0,T,M,n,lane);  __syncwarp();
    for (int i=lane;i<n2;i+=32)
        g_D[b*165 + d_LOFF[l] + i] = (float)M[i];

    if (l==0 && lane==0){
        double K[3][3];
        for (int r=0;r<3;r++) for (int c=0;c<3;c++) K[r][c]=(double)intr[b*9+r*3+c];
        double det = K[0][0]*(K[1][1]*K[2][2]-K[1][2]*K[2][1])
                   - K[0][1]*(K[1][0]*K[2][2]-K[1][2]*K[2][0])
                   + K[0][2]*(K[1][0]*K[2][1]-K[1][1]*K[2][0]);
        double id = 1.0/det;
        double Ki[3][3];
        Ki[0][0]=(K[1][1]*K[2][2]-K[1][2]*K[2][1])*id;
        Ki[0][1]=(K[0][2]*K[2][1]-K[0][1]*K[2][2])*id;
        Ki[0][2]=(K[0][1]*K[1][2]-K[0][2]*K[1][1])*id;
        Ki[1][0]=(K[1][2]*K[2][0]-K[1][0]*K[2][2])*id;
        Ki[1][1]=(K[0][0]*K[2][2]-K[0][2]*K[2][0])*id;
        Ki[1][2]=(K[0][2]*K[1][0]-K[0][0]*K[1][2])*id;
        Ki[2][0]=(K[1][0]*K[2][1]-K[1][1]*K[2][0])*id;
        Ki[2][1]=(K[0][1]*K[2][0]-K[0][0]*K[2][1])*id;
        Ki[2][2]=(K[0][0]*K[1][1]-K[0][1]*K[1][0])*id;

        int Hh = read_dim(ph, 128);
        int Ww = read_dim(pw, 128);
        double psx = 1.0/(double)Ww, psy = 1.0/(double)Hh;
        double d2  = K[0][0]*K[1][1]-K[0][1]*K[1][0];
        double v0  = ( K[1][1]*psx - K[0][1]*psy)/d2;
        double v1  = (-K[1][0]*psx + K[0][0]*psy)/d2;
        double mult = 0.1*(v0+v1);

        float* cb = g_cb + b*24;
        for (int r=0;r<3;r++) for (int c=0;c<3;c++) cb[r*3+c]=(float)ext[b*16+r*4+c];
        for (int r=0;r<3;r++) cb[9+r]=(float)ext[b*16+r*4+3];
        for (int r=0;r<3;r++) for (int c=0;c<3;c++) cb[12+r*3+c]=(float)Ki[r][c];
        cb[21]=(float)mult;
    }
}

/* ------------------------------------------------------------------ */
/* Kernel 4: main per-gaussian kernel.                                */
/* smem: one padded row per gaussian, SH computed IN PLACE:           */
/*   slots 0-2 scales, 3-6 quat, 7-81 rotated SH. means+cov separate. */
__global__ void __launch_bounds__(GPB)
gauss_kernel(const float* __restrict__ coords, const float* __restrict__ depths,
             const float* __restrict__ opac,   const float* __restrict__ raw,
             float* __restrict__ out){
    extern __shared__ float sm[];
    float* s_in = sm;                 /* GPB*83 (row stride 83, odd => conflict-free) */
    float* s_mc = s_in + GPB*83;      /* GPB*13 : means(3)+cov(9), stride 13 */
    float* s_D  = s_mc + GPB*13;      /* 165 */
    float* s_cb = s_D  + 165;         /* 24  */

    const int tid = threadIdx.x;
    const int g0  = blockIdx.x*GPB;
    const int b   = g0/(HWD*SPPX);

    for (int i=tid;i<165;i+=GPB) s_D[i] = g_D[b*165+i];
    if (tid < 24) s_cb[tid] = g_cb[b*24+tid];

    /* stage raw_gaussians: coalesced float4 loads -> padded rows */
    {
        const float4* src = reinterpret_cast<const float4*>(raw + (size_t)g0*82);
        #pragma unroll 4
        for (int i=tid; i<GPB*82/4; i+=GPB){
            float4 v = src[i];
            int lin = i*4;
            float vv[4] = {v.x, v.y, v.z, v.w};
            #pragma unroll
            for (int w=0; w<4; w++){
                int t = (lin+w)/82;
                int j = (lin+w) - t*82;
                s_in[t*83 + j] = vv[w];
            }
        }
    }
    __syncthreads();

    const int g = g0 + tid;
    float* in = s_in + tid*83;
    const float  depth = depths[g];
    const float2 uv = reinterpret_cast<const float2*>(coords)[g];
    out[OFF_OPA + g] = opac[g];

    /* scales */
    const float mult = s_cb[21];
    float sc[3];
    #pragma unroll
    for (int i=0;i<3;i++){
        float x = in[i];
        float sig = 1.0f/(1.0f+expf(-x));
        sc[i] = (0.5f + 14.5f*sig) * depth * mult;
    }
    /* quaternion -> rotation */
    float q0=in[3], q1=in[4], q2=in[5], q3=in[6];
    float nq = sqrtf(q0*q0+q1*q1+q2*q2+q3*q3);
    float invq = 1.0f/(nq + 1e-8f);
    q0*=invq; q1*=invq; q2*=invq; q3*=invq;
    float ss = 2.0f/(q0*q0+q1*q1+q2*q2+q3*q3);
    const float r=q0, ii=q1, jj=q2, kk=q3;
    float R00=1.f-ss*(jj*jj+kk*kk), R01=ss*(ii*jj-kk*r), R02=ss*(ii*kk+jj*r);
    float R10=ss*(ii*jj+kk*r), R11=1.f-ss*(ii*ii+kk*kk), R12=ss*(jj*kk-ii*r);
    float R20=ss*(ii*kk-jj*r), R21=ss*(jj*kk+ii*r), R22=1.f-ss*(ii*ii+jj*jj);
    float v0=sc[0]*sc[0], v1=sc[1]*sc[1], v2=sc[2]*sc[2];

    {
        float* mc = s_mc + tid*13;
        /* means */
        float dx = s_cb[12]*uv.x + s_cb[13]*uv.y + s_cb[14];
        float dy = s_cb[15]*uv.x + s_cb[16]*uv.y + s_cb[17];
        float dz = s_cb[18]*uv.x + s_cb[19]*uv.y + s_cb[20];
        float dn = 1.0f/sqrtf(dx*dx+dy*dy+dz*dz);
        dx*=dn; dy*=dn; dz*=dn;
        float wx = s_cb[0]*dx + s_cb[1]*dy + s_cb[2]*dz;
        float wy = s_cb[3]*dx + s_cb[4]*dy + s_cb[5]*dz;
        float wz = s_cb[6]*dx + s_cb[7]*dy + s_cb[8]*dz;
        mc[0] = s_cb[9]  + wx*depth;
        mc[1] = s_cb[10] + wy*depth;
        mc[2] = s_cb[11] + wz*depth;
        /* covariance */
        float c00=R00*R00*v0+R01*R01*v1+R02*R02*v2;
        float c01=R00*R10*v0+R01*R11*v1+R02*R12*v2;
        float c02=R00*R20*v0+R01*R21*v1+R02*R22*v2;
        float c11=R10*R10*v0+R11*R11*v1+R12*R12*v2;
        float c12=R10*R20*v0+R11*R21*v1+R12*R22*v2;
        float c22=R20*R20*v0+R21*R21*v1+R22*R22*v2;
        mc[3]=c00; mc[4]=c01; mc[5]=c02;
        mc[6]=c01; mc[7]=c11; mc[8]=c12;
        mc[9]=c02; mc[10]=c12; mc[11]=c22;
    }

    /* SH rotation IN PLACE: sho_i = sum_j D_l[i][j]*(mask_l*shin_j) */
    {
        const int   LOFFc[5] = {0,1,10,35,84};
        const float MSK[5]   = {1.0f, 0.025f, 0.00625f, 0.0015625f, 0.000390625f};
        #pragma unroll
        for (int ch=0; ch<3; ch++){
            float* shp = in + 7 + ch*25;
            shp[0] = s_D[0]*shp[0];
            #pragma unroll
            for (int l=1;l<5;l++){
                const int n = 2*l+1, off = l*l;
                const float* D = s_D + LOFFc[l];
                float t[9];
                #pragma unroll
                for (int j=0;j<n;j++) t[j] = shp[off+j]*MSK[l];
                #pragma unroll
                for (int i=0;i<n;i++){
                    float s = 0.f;
                    #pragma unroll
                    for (int j=0;j<n;j++) s += D[i*n+j]*t[j];
                    shp[off+i] = s;
                }
            }
        }
    }
    /* stash scales + normalized quat into freed slots */
    in[0]=sc[0]; in[1]=sc[1]; in[2]=sc[2];
    in[3]=q0; in[4]=q1; in[5]=q2; in[6]=q3;
    __syncthreads();

    /* coalesced float4 flush from padded rows */
    {
        /* SH: 75 floats/row from slot 7 */
        float4* d4 = (float4*)(out + OFF_SH + (size_t)g0*75);
        #pragma unroll 4
        for (int i=tid; i<GPB*75/4; i+=GPB){
            int lin = i*4; float vv[4];
            #pragma unroll
            for (int w=0;w<4;w++){
                int idx=lin+w, t=idx/75, j=idx-t*75;
                vv[w] = s_in[t*83+7+j];
            }
            d4[i] = make_float4(vv[0],vv[1],vv[2],vv[3]);
        }
        /* means */
        d4 = (float4*)(out + OFF_MEANS + (size_t)g0*3);
        for (int i=tid; i<GPB*3/4; i+=GPB){
            int lin=i*4; float vv[4];
            #pragma unroll
            for (int w=0;w<4;w++){
                int idx=lin+w, t=idx/3, j=idx-t*3;
                vv[w] = s_mc[t*13+j];
            }
            d4[i] = make_float4(vv[0],vv[1],vv[2],vv[3]);
        }
        /* covariance */
        d4 = (float4*)(out + OFF_COV + (size_t)g0*9);
        #pragma unroll 2
        for (int i=tid; i<GPB*9/4; i+=GPB){
            int lin=i*4; float vv[4];
            #pragma unroll
            for (int w=0;w<4;w++){
                int idx=lin+w, t=idx/9, j=idx-t*9;
                vv[w] = s_mc[t*13+3+j];
            }
            d4[i] = make_float4(vv[0],vv[1],vv[2],vv[3]);
        }
        /* scales */
        d4 = (float4*)(out + OFF_SCL + (size_t)g0*3);
        for (int i=tid; i<GPB*3/4; i+=GPB){
            int lin=i*4; float vv[4];
            #pragma unroll
            for (int w=0;w<4;w++){
                int idx=lin+w, t=idx/3, j=idx-t*3;
                vv[w] = s_in[t*83+j];
            }
            d4[i] = make_float4(vv[0],vv[1],vv[2],vv[3]);
        }
        /* rotations: 4 floats/row -> one float4 per gaussian */
        d4 = (float4*)(out + OFF_ROT + (size_t)g0*4);
        for (int i=tid; i<GPB; i+=GPB){
            const float* rt = s_in + i*83 + 3;
            d4[i] = make_float4(rt[0],rt[1],rt[2],rt[3]);
        }
    }
}

/* ------------------------------------------------------------------ */
/* Kernel 5: features = transpose(grd_feat) broadcast over SPP        */
__global__ void feat_kernel(const float* __restrict__ gf, float* __restrict__ out){
    __shared__ float tile[64][33];
    const int b   = blockIdx.y;
    const int hw0 = blockIdx.x*32;
    const int tx  = threadIdx.x;       /* 0..31 */
    const int ty  = threadIdx.y;       /* 0..7  */

    const float* src = gf + (size_t)b*CCH*HWD + hw0;
    #pragma unroll
    for (int c=ty; c<64; c+=8) tile[c][tx] = src[(size_t)c*HWD + tx];
    __syncthreads();

    #pragma unroll
    for (int k=0;k<4;k++){
        int hwl = ty + 8*k;
        size_t gbase = ((size_t)(b*HWD + hw0 + hwl))*SPPX;
        float a = tile[tx][hwl];
        float bb2 = tile[tx+32][hwl];
        #pragma unroll
        for (int spp=0; spp<SPPX; spp++){
            float* o = out + OFF_FEAT + (gbase+spp)*64;
            o[tx]    = a;
            o[tx+32] = bb2;
        }
    }
}

/* ------------------------------------------------------------------ */
extern "C" void kernel_launch(void* const* d_in, const int* in_sizes, int n_in,
                              void* d_out, int out_size){
    const float* ext    = (const float*)d_in[0];
    const float* intr   = (const float*)d_in[1];
    const float* coords = (const float*)d_in[2];
    const float* depths = (const float*)d_in[3];
    const float* opac   = (const float*)d_in[4];
    const float* raw    = (const float*)d_in[5];
    const float* gf     = (const float*)d_in[6];
    const void*  ph     = (n_in > 7) ? d_in[7] : nullptr;
    const void*  pw     = (n_in > 8) ? d_in[8] : nullptr;
    float* out = (float*)d_out;

    setup_gen_kernel<<<5, 32>>>();
    setup_exp_kernel<<<BB*5*3, 32>>>(ext);
    setup_combine_kernel<<<BB*5, 32>>>(ext, intr, ph, pw);

    size_t smem = (size_t)(GPB*83 + GPB*13 + 165 + 24)*sizeof(float);
    cudaFuncSetAttribute(gauss_kernel, cudaFuncAttributeMaxDynamicSharedMemorySize, (int)smem);
    gauss_kernel<<<NG/GPB, GPB, smem>>>(coords, depths, opac, raw, out);

    feat_kernel<<<dim3(HWD/32, BB), dim3(32,8)>>>(gf, out);
}

// round 7
// speedup vs baseline: 2.1194x; 1.2610x over previous
#include <cuda_runtime.h>
#include <math.h>

#define BB   4
#define HWD  16384
#define SPPX 3
#define CCH  64
#define NG   (BB*HWD*SPPX)      /* 196608 gaussians */
#define GPB  128                /* gaussians per block */
#define NGB  (HWD*SPPX)         /* gaussians per batch = 49152 */
#define NHW  44                 /* hw rows per block tile */
#define FTS  68                 /* feat tile row stride (16B aligned) */

/* output layout (floats): means|cov|sh|opa|feat|scales|rot */
#define OFF_MEANS ((size_t)0)
#define OFF_COV   ((size_t)3*NG)
#define OFF_SH    ((size_t)12*NG)
#define OFF_OPA   ((size_t)87*NG)
#define OFF_FEAT  ((size_t)88*NG)
#define OFF_SCL   ((size_t)152*NG)
#define OFF_ROT   ((size_t)155*NG)

static __device__ const int d_LOFF[5] = {0,1,10,35,84};

__device__ float g_D[BB*165];   /* Wigner D per batch, concat l=0..4 */
__device__ float g_cb[BB*24];   /* per-batch consts: R(9) o(3) Kinv(9) mult */

/* ------------------------------------------------------------------ */
/* fp32 warp-parallel n x n matmul + expm (scaling & squaring)        */
__device__ __forceinline__ void wmmf(const float* A, const float* B, float* C,
                                     int n, int lane){
    for (int idx=lane; idx<n*n; idx+=32){
        int r=idx/n, c=idx-r*n;
        float s=0.f;
        for (int k=0;k<n;k++) s += A[r*n+k]*B[k*n+c];
        C[idx]=s;
    }
}

__device__ void wexpmf(float theta, const float* G, int n, int lane,
                       float* M, float* P, float* T){
    const int n2=n*n;
    for (int i=lane;i<n2;i+=32) M[i]=theta*G[i];
    __syncwarp();
    int s=0;
    if (lane==0){
        float nm=0.f;
        for (int r=0;r<n;r++){
            float rs=0.f;
            for (int c=0;c<n;c++) rs += fabsf(M[r*n+c]);
            nm = fmaxf(nm, rs);
        }
        while (nm > 1.0f){ nm*=0.5f; s++; }
    }
    s = __shfl_sync(0xffffffffu, s, 0);
    float scl = ldexpf(1.0f, -s);
    for (int i=lane;i<n2;i+=32) M[i]*=scl;
    __syncwarp();
    for (int i=lane;i<n2;i+=32) P[i] = ((i/n)==(i%n)) ? 1.0f : 0.0f;
    __syncwarp();
    for (int k=13;k>=1;k--){
        wmmf(M,P,T,n,lane); __syncwarp();
        float ik = 1.0f/(float)k;
        for (int i=lane;i<n2;i+=32)
            P[i] = T[i]*ik + (((i/n)==(i%n)) ? 1.0f : 0.0f);
        __syncwarp();
    }
    for (int it=0; it<s; it++){
        wmmf(P,P,T,n,lane); __syncwarp();
        for (int i=lane;i<n2;i+=32) P[i]=T[i];
        __syncwarp();
    }
}

__device__ __forceinline__ int read_dim(const void* p, int defv){
    if (!p) return defv;
    int iv = *(const int*)p;
    if (iv>=1 && iv<=(1<<20)) return iv;
    float fv = *(const float*)p;
    if (fv>=1.0f && fv<=1048576.0f) return (int)(fv+0.5f);
    return defv;
}

/* ------------------------------------------------------------------ */
/* ONE fused setup kernel: grid = BB*5 (b,l), block = 32.             */
/* Builds generators, angles, 3 expms, combine, writes g_D (+ g_cb).  */
__global__ void setup_kernel(const float* __restrict__ ext,
                             const float* __restrict__ intr,
                             const void* ph, const void* pw){
    const int b = blockIdx.x/5, l = blockIdx.x%5;
    const int n = 2*l+1, n2 = n*n;
    const int lane = threadIdx.x;
    __shared__ float Qre[81],Qim[81],Xre[81],Xim[81],Tre[81],Tim[81];
    __shared__ float Gx[81],Gy[81];
    __shared__ float M[81],P[81],W[81],EA[81],EB[81],EC[81];

    /* ---- build complex change-of-basis Q ---- */
    for (int i=lane;i<n2;i+=32){ Qre[i]=0.f; Qim[i]=0.f; }
    __syncwarp();
    if (lane==0){
        const float is2 = 0.70710678118654752440f;
        for (int m=-l;m<0;m++){
            Qre[(l+m)*n+(l-m)] = is2;
            Qim[(l+m)*n+(l+m)] = -is2;
        }
        Qre[l*n+l] = 1.0f;
        for (int m=1;m<=l;m++){
            float sg = (m&1)? -1.0f : 1.0f;
            Qre[(l+m)*n+(l+m)] = sg*is2;
            Qim[(l+m)*n+(l-m)] = sg*is2;
        }
    }
    __syncwarp();
    { /* multiply by (-i)^l */
        float cr,ci;
        switch (l&3){
            case 0: cr=1;  ci=0;  break;
            case 1: cr=0;  ci=-1; break;
            case 2: cr=-1; ci=0;  break;
            default:cr=0;  ci=1;  break;
        }
        for (int i=lane;i<n2;i+=32){
            float re=Qre[i], im=Qim[i];
            Qre[i]=re*cr-im*ci; Qim[i]=re*ci+im*cr;
        }
    }
    __syncwarp();

    /* ---- generators a=0 (x) and a=1 (y): G = Re(Q^H X Q) ---- */
    for (int a=0;a<2;a++){
        for (int i=lane;i<n2;i+=32){ Xre[i]=0.f; Xim[i]=0.f; }
        __syncwarp();
        if (lane==0){
            float jj=(float)l;
            if (a==1){
                for (int i=0;i<n;i++) Xim[i*n+i] = (float)(-l+i);
            } else {
                for (int i=0;i<n-1;i++){
                    float m = -jj + (float)i;
                    float sq = sqrtf(jj*(jj+1.0f) - m*(m+1.0f));
                    Xre[(i+1)*n+i] = -0.5f*sq; Xre[i*n+(i+1)] = 0.5f*sq;
                }
            }
        }
        __syncwarp();
        for (int idx=lane; idx<n2; idx+=32){
            int r=idx/n, c=idx-r*n;
            float sre=0.f, sim=0.f;
            for (int k=0;k<n;k++){
                float xr=Xre[r*n+k], xi=Xim[r*n+k];
                float qr=Qre[k*n+c], qi=Qim[k*n+c];
                sre += xr*qr - xi*qi;
                sim += xr*qi + xi*qr;
            }
            Tre[idx]=sre; Tim[idx]=sim;
        }
        __syncwarp();
        float* G = (a==0)? Gx : Gy;
        for (int idx=lane; idx<n2; idx+=32){
            int r=idx/n, c=idx-r*n;
            float s=0.f;
            for (int k=0;k<n;k++)
                s += Qre[k*n+r]*Tre[k*n+c] + Qim[k*n+r]*Tim[k*n+c];
            G[idx] = s;
        }
        __syncwarp();
    }

    /* ---- angles from extrinsics ---- */
    float al=0.f, be=0.f, ga=0.f;
    if (lane==0){
        float R[3][3];
        for (int r=0;r<3;r++) for (int c=0;c<3;c++) R[r][c] = ext[b*16+r*4+c];
        float x0=R[0][1], x1=R[1][1], x2=R[2][1];
        float inv = 1.0f/sqrtf(x0*x0+x1*x1+x2*x2);
        x0*=inv; x1*=inv; x2*=inv;
        be = acosf(fminf(1.0f, fmaxf(-1.0f, x1)));
        al = atan2f(x0, x2);
        float ca=cosf(al), sa=sinf(al);
        float Rp00 = ca*R[0][0] - sa*R[2][0];
        float Rp02 = ca*R[0][2] - sa*R[2][2];
        ga = atan2f(Rp02, Rp00);
    }
    al = __shfl_sync(0xffffffffu, al, 0);
    be = __shfl_sync(0xffffffffu, be, 0);
    ga = __shfl_sync(0xffffffffu, ga, 0);

    /* ---- three expms + combine: D = e^{al Xy} e^{-be Xx} e^{ga Xy} ---- */
    wexpmf(al,  Gy, n, lane, M,P,W);
    for (int i=lane;i<n2;i+=32) EA[i]=P[i];
    __syncwarp();
    wexpmf(-be, Gx, n, lane, M,P,W);
    for (int i=lane;i<n2;i+=32) EB[i]=P[i];
    __syncwarp();
    wexpmf(ga,  Gy, n, lane, M,P,W);
    for (int i=lane;i<n2;i+=32) EC[i]=P[i];
    __syncwarp();
    wmmf(EB,EC,W,n,lane); __syncwarp();
    wmmf(EA,W,M,n,lane);  __syncwarp();
    for (int i=lane;i<n2;i+=32)
        g_D[b*165 + d_LOFF[l] + i] = M[i];

    /* ---- per-batch constants (once, on the l==0 block) ---- */
    if (l==0 && lane==0){
        float K[3][3];
        for (int r=0;r<3;r++) for (int c=0;c<3;c++) K[r][c]=intr[b*9+r*3+c];
        float det = K[0][0]*(K[1][1]*K[2][2]-K[1][2]*K[2][1])
                  - K[0][1]*(K[1][0]*K[2][2]-K[1][2]*K[2][0])
                  + K[0][2]*(K[1][0]*K[2][1]-K[1][1]*K[2][0]);
        float id = 1.0f/det;
        float Ki[3][3];
        Ki[0][0]=(K[1][1]*K[2][2]-K[1][2]*K[2][1])*id;
        Ki[0][1]=(K[0][2]*K[2][1]-K[0][1]*K[2][2])*id;
        Ki[0][2]=(K[0][1]*K[1][2]-K[0][2]*K[1][1])*id;
        Ki[1][0]=(K[1][2]*K[2][0]-K[1][0]*K[2][2])*id;
        Ki[1][1]=(K[0][0]*K[2][2]-K[0][2]*K[2][0])*id;
        Ki[1][2]=(K[0][2]*K[1][0]-K[0][0]*K[1][2])*id;
        Ki[2][0]=(K[1][0]*K[2][1]-K[1][1]*K[2][0])*id;
        Ki[2][1]=(K[0][1]*K[2][0]-K[0][0]*K[2][1])*id;
        Ki[2][2]=(K[0][0]*K[1][1]-K[0][1]*K[1][0])*id;

        int Hh = read_dim(ph, 128);
        int Ww = read_dim(pw, 128);
        float psx = 1.0f/(float)Ww, psy = 1.0f/(float)Hh;
        float d2  = K[0][0]*K[1][1]-K[0][1]*K[1][0];
        float v0  = ( K[1][1]*psx - K[0][1]*psy)/d2;
        float v1  = (-K[1][0]*psx + K[0][0]*psy)/d2;
        float mult = 0.1f*(v0+v1);

        float* cb = g_cb + b*24;
        for (int r=0;r<3;r++) for (int c=0;c<3;c++) cb[r*3+c]=ext[b*16+r*4+c];
        for (int r=0;r<3;r++) cb[9+r]=ext[b*16+r*4+3];
        for (int r=0;r<3;r++) for (int c=0;c<3;c++) cb[12+r*3+c]=Ki[r][c];
        cb[21]=mult;
    }
}

/* ------------------------------------------------------------------ */
/* Main per-gaussian kernel, feat writes fused in.                    */
__global__ void __launch_bounds__(GPB)
gauss_kernel(const float* __restrict__ coords, const float* __restrict__ depths,
             const float* __restrict__ opac,   const float* __restrict__ raw,
             const float* __restrict__ gf,     float* __restrict__ out){
    extern __shared__ float sm[];
    float* s_in = sm;                  /* GPB*83 (odd stride, conflict-free) */
    float* s_mc = s_in + GPB*83;       /* GPB*13 : means(3)+cov(9)           */
    float* s_ft = s_mc + GPB*13;       /* NHW*FTS feat tile [hw][c]          */
    float* s_D  = s_ft + NHW*FTS;      /* 165 (mask folded in)               */
    float* s_cb = s_D  + 165;          /* 24                                 */

    const int tid  = threadIdx.x;
    const int g0   = blockIdx.x*GPB;
    const int b    = g0/NGB;
    const int idx0 = g0 - b*NGB;
    const int hw0  = idx0/3;

    {
        const float MSK[5] = {1.0f, 0.025f, 0.00625f, 0.0015625f, 0.000390625f};
        for (int i=tid;i<165;i+=GPB){
            int l = (i>=84)?4:(i>=35)?3:(i>=10)?2:(i>=1)?1:0;
            s_D[i] = g_D[b*165+i]*MSK[l];
        }
    }
    if (tid < 24) s_cb[tid] = g_cb[b*24+tid];

    /* stage feat tile: [hw][c], coalesced gmem reads */
    {
        const float* gfb = gf + (size_t)b*CCH*HWD;
        #pragma unroll 4
        for (int i=tid; i<CCH*NHW; i+=GPB){
            int c = i/NHW, j = i - c*NHW;
            int hwrow = hw0 + j;
            float v = (hwrow < HWD) ? gfb[(size_t)c*HWD + hwrow] : 0.f;
            s_ft[j*FTS + c] = v;
        }
    }

    /* stage raw_gaussians: coalesced float4 loads -> padded rows */
    {
        const float4* src = reinterpret_cast<const float4*>(raw + (size_t)g0*82);
        #pragma unroll 4
        for (int i=tid; i<GPB*82/4; i+=GPB){
            float4 v = src[i];
            int lin = i*4;
            float vv[4] = {v.x, v.y, v.z, v.w};
            #pragma unroll
            for (int w=0; w<4; w++){
                int t = (lin+w)/82;
                int j = (lin+w) - t*82;
                s_in[t*83 + j] = vv[w];
            }
        }
    }
    __syncthreads();

    const int g = g0 + tid;
    float* in = s_in + tid*83;
    const float  depth = depths[g];
    const float2 uv = reinterpret_cast<const float2*>(coords)[g];
    out[OFF_OPA + g] = opac[g];

    /* scales */
    const float mult = s_cb[21];
    float sc[3];
    #pragma unroll
    for (int i=0;i<3;i++){
        float x = in[i];
        float sig = 1.0f/(1.0f+expf(-x));
        sc[i] = (0.5f + 14.5f*sig) * depth * mult;
    }
    /* quaternion -> rotation */
    float q0=in[3], q1=in[4], q2=in[5], q3=in[6];
    float nq = sqrtf(q0*q0+q1*q1+q2*q2+q3*q3);
    float invq = 1.0f/(nq + 1e-8f);
    q0*=invq; q1*=invq; q2*=invq; q3*=invq;
    float ss = 2.0f/(q0*q0+q1*q1+q2*q2+q3*q3);
    const float r=q0, ii=q1, jj=q2, kk=q3;
    float R00=1.f-ss*(jj*jj+kk*kk), R01=ss*(ii*jj-kk*r), R02=ss*(ii*kk+jj*r);
    float R10=ss*(ii*jj+kk*r), R11=1.f-ss*(ii*ii+kk*kk), R12=ss*(jj*kk-ii*r);
    float R20=ss*(ii*kk-jj*r), R21=ss*(jj*kk+ii*r), R22=1.f-ss*(ii*ii+jj*jj);
    float v0=sc[0]*sc[0], v1=sc[1]*sc[1], v2=sc[2]*sc[2];

    {
        float* mc = s_mc + tid*13;
        float dx = s_cb[12]*uv.x + s_cb[13]*uv.y + s_cb[14];
        float dy = s_cb[15]*uv.x + s_cb[16]*uv.y + s_cb[17];
        float dz = s_cb[18]*uv.x + s_cb[19]*uv.y + s_cb[20];
        float dn = 1.0f/sqrtf(dx*dx+dy*dy+dz*dz);
        dx*=dn; dy*=dn; dz*=dn;
        float wx = s_cb[0]*dx + s_cb[1]*dy + s_cb[2]*dz;
        float wy = s_cb[3]*dx + s_cb[4]*dy + s_cb[5]*dz;
        float wz = s_cb[6]*dx + s_cb[7]*dy + s_cb[8]*dz;
        mc[0] = s_cb[9]  + wx*depth;
        mc[1] = s_cb[10] + wy*depth;
        mc[2] = s_cb[11] + wz*depth;
        float c00=R00*R00*v0+R01*R01*v1+R02*R02*v2;
        float c01=R00*R10*v0+R01*R11*v1+R02*R12*v2;
        float c02=R00*R20*v0+R01*R21*v1+R02*R22*v2;
        float c11=R10*R10*v0+R11*R11*v1+R12*R12*v2;
        float c12=R10*R20*v0+R11*R21*v1+R12*R22*v2;
        float c22=R20*R20*v0+R21*R21*v1+R22*R22*v2;
        mc[3]=c00; mc[4]=c01; mc[5]=c02;
        mc[6]=c01; mc[7]=c11; mc[8]=c12;
        mc[9]=c02; mc[10]=c12; mc[11]=c22;
    }

    /* SH rotation IN PLACE, 3 channels fused, mask already in s_D */
    {
        float* shp = in + 7;
        const float d0 = s_D[0];
        shp[0]*=d0; shp[25]*=d0; shp[50]*=d0;
        const int LOFFc[5] = {0,1,10,35,84};
        #pragma unroll
        for (int l=1;l<5;l++){
            const int n = 2*l+1, off = l*l;
            const float* D = s_D + LOFFc[l];
            float t0[9], t1[9], t2[9];
            #pragma unroll
            for (int j=0;j<n;j++){
                t0[j]=shp[off+j]; t1[j]=shp[25+off+j]; t2[j]=shp[50+off+j];
            }
            #pragma unroll
            for (int i=0;i<n;i++){
                float a0=0.f, a1=0.f, a2=0.f;
                #pragma unroll
                for (int j=0;j<n;j++){
                    float d = D[i*n+j];
                    a0 += d*t0[j]; a1 += d*t1[j]; a2 += d*t2[j];
                }
                shp[off+i]=a0; shp[25+off+i]=a1; shp[50+off+i]=a2;
            }
        }
    }
    /* stash scales + normalized quat into freed slots */
    in[0]=sc[0]; in[1]=sc[1]; in[2]=sc[2];
    in[3]=q0; in[4]=q1; in[5]=q2; in[6]=q3;
    __syncthreads();

    /* coalesced float4 flush */
    {
        /* SH */
        float4* d4 = (float4*)(out + OFF_SH + (size_t)g0*75);
        #pragma unroll 4
        for (int i=tid; i<GPB*75/4; i+=GPB){
            int lin = i*4; float vv[4];
            #pragma unroll
            for (int w=0;w<4;w++){
                int idx=lin+w, t=idx/75, j=idx-t*75;
                vv[w] = s_in[t*83+7+j];
            }
            d4[i] = make_float4(vv[0],vv[1],vv[2],vv[3]);
        }
        /* features: LDS128 from [hw][c] tile */
        d4 = (float4*)(out + OFF_FEAT + (size_t)g0*64);
        #pragma unroll 4
        for (int i=tid; i<GPB*64/4; i+=GPB){
            int lin = i*4;
            int gl  = lin>>6;
            int c0  = lin & 63;
            int hwl = (idx0+gl)/3 - hw0;
            d4[i] = *reinterpret_cast<const float4*>(&s_ft[hwl*FTS + c0]);
        }
        /* means */
        d4 = (float4*)(out + OFF_MEANS + (size_t)g0*3);
        for (int i=tid; i<GPB*3/4; i+=GPB){
            int lin=i*4; float vv[4];
            #pragma unroll
            for (int w=0;w<4;w++){
                int idx=lin+w, t=idx/3, j=idx-t*3;
                vv[w] = s_mc[t*13+j];
            }
            d4[i] = make_float4(vv[0],vv[1],vv[2],vv[3]);
        }
        /* covariance */
        d4 = (float4*)(out + OFF_COV + (size_t)g0*9);
        #pragma unroll 2
        for (int i=tid; i<GPB*9/4; i+=GPB){
            int lin=i*4; float vv[4];
            #pragma unroll
            for (int w=0;w<4;w++){
                int idx=lin+w, t=idx/9, j=idx-t*9;
                vv[w] = s_mc[t*13+3+j];
            }
            d4[i] = make_float4(vv[0],vv[1],vv[2],vv[3]);
        }
        /* scales */
        d4 = (float4*)(out + OFF_SCL + (size_t)g0*3);
        for (int i=tid; i<GPB*3/4; i+=GPB){
            int lin=i*4; float vv[4];
            #pragma unroll
            for (int w=0;w<4;w++){
                int idx=lin+w, t=idx/3, j=idx-t*3;
                vv[w] = s_in[t*83+j];
            }
            d4[i] = make_float4(vv[0],vv[1],vv[2],vv[3]);
        }
        /* rotations */
        d4 = (float4*)(out + OFF_ROT + (size_t)g0*4);
        for (int i=tid; i<GPB; i+=GPB){
            const float* rt = s_in + i*83 + 3;
            d4[i] = make_float4(rt[0],rt[1],rt[2],rt[3]);
        }
    }
}

/* ------------------------------------------------------------------ */
extern "C" void kernel_launch(void* const* d_in, const int* in_sizes, int n_in,
                              void* d_out, int out_size){
    const float* ext    = (const float*)d_in[0];
    const float* intr   = (const float*)d_in[1];
    const float* coords = (const float*)d_in[2];
    const float* depths = (const float*)d_in[3];
    const float* opac   = (const float*)d_in[4];
    const float* raw    = (const float*)d_in[5];
    const float* gf     = (const float*)d_in[6];
    const void*  ph     = (n_in > 7) ? d_in[7] : nullptr;
    const void*  pw     = (n_in > 8) ? d_in[8] : nullptr;
    float* out = (float*)d_out;

    setup_kernel<<<BB*5, 32>>>(ext, intr, ph, pw);

    size_t smem = (size_t)(GPB*83 + GPB*13 + NHW*FTS + 165 + 24)*sizeof(float);
    cudaFuncSetAttribute(gauss_kernel, cudaFuncAttributeMaxDynamicSharedMemorySize, (int)smem);
    gauss_kernel<<<NG/GPB, GPB, smem>>>(coords, depths, opac, raw, gf, out);
}

// round 8
// speedup vs baseline: 3.3863x; 1.5978x over previous
#include <cuda_runtime.h>
#include <math.h>

#define BB   4
#define HWD  16384
#define SPPX 3
#define CCH  64
#define NG   (BB*HWD*SPPX)      /* 196608 gaussians */
#define GPB  128                /* gaussians per block */
#define NGB  (HWD*SPPX)         /* gaussians per batch = 49152 */
#define NHW  44                 /* hw rows per block tile */
#define FTS  68                 /* feat tile row stride (16B aligned) */

/* output layout (floats): means|cov|sh|opa|feat|scales|rot */
#define OFF_MEANS ((size_t)0)
#define OFF_COV   ((size_t)3*NG)
#define OFF_SH    ((size_t)12*NG)
#define OFF_OPA   ((size_t)87*NG)
#define OFF_FEAT  ((size_t)88*NG)
#define OFF_SCL   ((size_t)152*NG)
#define OFF_ROT   ((size_t)155*NG)

static __device__ const int d_LOFF[5] = {0,1,10,35,84};

__device__ float g_D[BB*165];   /* Wigner D per batch, concat l=0..4 */
__device__ float g_cb[BB*24];   /* per-batch consts: R(9) o(3) Kinv(9) mult */

/* ------------------------------------------------------------------ */
__device__ __forceinline__ void wmmf(const float* A, const float* B, float* C,
                                     int n, int lane){
    for (int idx=lane; idx<n*n; idx+=32){
        int r=idx/n, c=idx-r*n;
        float s=0.f;
        for (int k=0;k<n;k++) s += A[r*n+k]*B[k*n+c];
        C[idx]=s;
    }
}

/* Taylor expm (9 terms, threshold 1.0, scaling & squaring) */
__device__ void wexpmf(float theta, const float* G, int n, int lane,
                       float* M, float* P, float* T){
    const int n2=n*n;
    for (int i=lane;i<n2;i+=32) M[i]=theta*G[i];
    __syncwarp();
    int s=0;
    if (lane==0){
        float nm=0.f;
        for (int r=0;r<n;r++){
            float rs=0.f;
            for (int c=0;c<n;c++) rs += fabsf(M[r*n+c]);
            nm = fmaxf(nm, rs);
        }
        while (nm > 1.0f){ nm*=0.5f; s++; }
    }
    s = __shfl_sync(0xffffffffu, s, 0);
    float scl = ldexpf(1.0f, -s);
    for (int i=lane;i<n2;i+=32) M[i]*=scl;
    __syncwarp();
    for (int i=lane;i<n2;i+=32) P[i] = ((i/n)==(i%n)) ? 1.0f : 0.0f;
    __syncwarp();
    for (int k=9;k>=1;k--){
        wmmf(M,P,T,n,lane); __syncwarp();
        float ik = 1.0f/(float)k;
        for (int i=lane;i<n2;i+=32)
            P[i] = T[i]*ik + (((i/n)==(i%n)) ? 1.0f : 0.0f);
        __syncwarp();
    }
    for (int it=0; it<s; it++){
        wmmf(P,P,T,n,lane); __syncwarp();
        for (int i=lane;i<n2;i+=32) P[i]=T[i];
        __syncwarp();
    }
}

__device__ __forceinline__ int read_dim(const void* p, int defv){
    if (!p) return defv;
    int iv = *(const int*)p;
    if (iv>=1 && iv<=(1<<20)) return iv;
    float fv = *(const float*)p;
    if (fv>=1.0f && fv<=1048576.0f) return (int)(fv+0.5f);
    return defv;
}

/* ------------------------------------------------------------------ */
/* ONE setup kernel: grid = BB*5 (b,l), block = 32.                   */
/* EA = e^{alpha X1}, EC = e^{gamma X1} in CLOSED FORM via            */
/*   e^{a X1} = Q^H diag(e^{i m a}) Q  (exact).                        */
/* EB = e^{-beta X0} via short Taylor. D = EA (EB EC).                 */
__global__ void setup_kernel(const float* __restrict__ ext,
                             const float* __restrict__ intr,
                             const void* ph, const void* pw){
    const int b = blockIdx.x/5, l = blockIdx.x%5;
    const int n = 2*l+1, n2 = n*n;
    const int lane = threadIdx.x;
    __shared__ float Qre[81],Qim[81],Sre[81],Sim[81],Tre[81],Tim[81];
    __shared__ float Gx[81],EA[81],EB[81],EC[81],M[81],P[81],W[81];
    __shared__ float cs[9], sn[9], cg[9], sg2[9];

    /* ---- complex change-of-basis Q, scaled by (-i)^l ---- */
    for (int i=lane;i<n2;i+=32){ Qre[i]=0.f; Qim[i]=0.f; }
    __syncwarp();
    if (lane==0){
        const float is2 = 0.70710678118654752440f;
        for (int m=-l;m<0;m++){
            Qre[(l+m)*n+(l-m)] = is2;
            Qim[(l+m)*n+(l+m)] = -is2;
        }
        Qre[l*n+l] = 1.0f;
        for (int m=1;m<=l;m++){
            float sgn = (m&1)? -1.0f : 1.0f;
            Qre[(l+m)*n+(l+m)] = sgn*is2;
            Qim[(l+m)*n+(l-m)] = sgn*is2;
        }
    }
    __syncwarp();
    {
        float cr,ci;
        switch (l&3){
            case 0: cr=1;  ci=0;  break;
            case 1: cr=0;  ci=-1; break;
            case 2: cr=-1; ci=0;  break;
            default:cr=0;  ci=1;  break;
        }
        for (int i=lane;i<n2;i+=32){
            float re=Qre[i], im=Qim[i];
            Qre[i]=re*cr-im*ci; Qim[i]=re*ci+im*cr;
        }
    }
    __syncwarp();

    /* ---- real generator Gx = Re(Q^H X0 Q) (X0 real antisym) ---- */
    for (int i=lane;i<n2;i+=32){ Sre[i]=0.f; Sim[i]=0.f; }
    __syncwarp();
    if (lane==0){
        float jj=(float)l;
        for (int i=0;i<n-1;i++){
            float m = -jj + (float)i;
            float sq = sqrtf(jj*(jj+1.0f) - m*(m+1.0f));
            Sre[(i+1)*n+i] = -0.5f*sq; Sre[i*n+(i+1)] = 0.5f*sq;
        }
    }
    __syncwarp();
    for (int idx=lane; idx<n2; idx+=32){
        int r=idx/n, c=idx-r*n;
        float sre=0.f, sim=0.f;
        for (int k=0;k<n;k++){
            float xr=Sre[r*n+k];
            float qr=Qre[k*n+c], qi=Qim[k*n+c];
            sre += xr*qr; sim += xr*qi;
        }
        Tre[idx]=sre; Tim[idx]=sim;
    }
    __syncwarp();
    for (int idx=lane; idx<n2; idx+=32){
        int r=idx/n, c=idx-r*n;
        float s=0.f;
        for (int k=0;k<n;k++)
            s += Qre[k*n+r]*Tre[k*n+c] + Qim[k*n+r]*Tim[k*n+c];
        Gx[idx] = s;
    }
    __syncwarp();

    /* ---- angles ---- */
    float al=0.f, be=0.f, ga=0.f;
    if (lane==0){
        float R[3][3];
        for (int r=0;r<3;r++) for (int c=0;c<3;c++) R[r][c] = ext[b*16+r*4+c];
        float x0=R[0][1], x1=R[1][1], x2=R[2][1];
        float inv = 1.0f/sqrtf(x0*x0+x1*x1+x2*x2);
        x0*=inv; x1*=inv; x2*=inv;
        be = acosf(fminf(1.0f, fmaxf(-1.0f, x1)));
        al = atan2f(x0, x2);
        float ca=cosf(al), sa=sinf(al);
        float Rp00 = ca*R[0][0] - sa*R[2][0];
        float Rp02 = ca*R[0][2] - sa*R[2][2];
        ga = atan2f(Rp02, Rp00);
    }
    al = __shfl_sync(0xffffffffu, al, 0);
    be = __shfl_sync(0xffffffffu, be, 0);
    ga = __shfl_sync(0xffffffffu, ga, 0);

    /* ---- EA, EC closed form ---- */
    if (lane < n){
        float m = (float)(lane - l);
        cs[lane] = cosf(m*al);  sn[lane]  = sinf(m*al);
        cg[lane] = cosf(m*ga);  sg2[lane] = sinf(m*ga);
    }
    __syncwarp();
    for (int idx=lane; idx<n2; idx+=32){
        int r=idx/n, c=idx-r*n;
        float sa_=0.f, sc_=0.f;
        for (int k=0;k<n;k++){
            float ar=Qre[k*n+r], ai=Qim[k*n+r];   /* conj(Q[k,r]) = ar - i ai */
            float br=Qre[k*n+c], bi=Qim[k*n+c];
            float pre = ar*br + ai*bi;            /* Re(conj(a)*b) */
            float pim = ar*bi - ai*br;            /* Im(conj(a)*b) */
            sa_ += pre*cs[k] - pim*sn[k];
            sc_ += pre*cg[k] - pim*sg2[k];
        }
        EA[idx]=sa_; EC[idx]=sc_;
    }
    __syncwarp();

    /* ---- EB = e^{-beta Gx} (Taylor) ---- */
    wexpmf(-be, Gx, n, lane, M,P,W);
    for (int i=lane;i<n2;i+=32) EB[i]=P[i];
    __syncwarp();

    /* ---- D = EA (EB EC) ---- */
    wmmf(EB,EC,W,n,lane); __syncwarp();
    wmmf(EA,W,M,n,lane);  __syncwarp();
    for (int i=lane;i<n2;i+=32)
        g_D[b*165 + d_LOFF[l] + i] = M[i];

    /* ---- per-batch constants ---- */
    if (l==0 && lane==0){
        float K[3][3];
        for (int r=0;r<3;r++) for (int c=0;c<3;c++) K[r][c]=intr[b*9+r*3+c];
        float det = K[0][0]*(K[1][1]*K[2][2]-K[1][2]*K[2][1])
                  - K[0][1]*(K[1][0]*K[2][2]-K[1][2]*K[2][0])
                  + K[0][2]*(K[1][0]*K[2][1]-K[1][1]*K[2][0]);
        float id = 1.0f/det;
        float Ki[3][3];
        Ki[0][0]=(K[1][1]*K[2][2]-K[1][2]*K[2][1])*id;
        Ki[0][1]=(K[0][2]*K[2][1]-K[0][1]*K[2][2])*id;
        Ki[0][2]=(K[0][1]*K[1][2]-K[0][2]*K[1][1])*id;
        Ki[1][0]=(K[1][2]*K[2][0]-K[1][0]*K[2][2])*id;
        Ki[1][1]=(K[0][0]*K[2][2]-K[0][2]*K[2][0])*id;
        Ki[1][2]=(K[0][2]*K[1][0]-K[0][0]*K[1][2])*id;
        Ki[2][0]=(K[1][0]*K[2][1]-K[1][1]*K[2][0])*id;
        Ki[2][1]=(K[0][1]*K[2][0]-K[0][0]*K[2][1])*id;
        Ki[2][2]=(K[0][0]*K[1][1]-K[0][1]*K[1][0])*id;

        int Hh = read_dim(ph, 128);
        int Ww = read_dim(pw, 128);
        float psx = 1.0f/(float)Ww, psy = 1.0f/(float)Hh;
        float d2  = K[0][0]*K[1][1]-K[0][1]*K[1][0];
        float v0  = ( K[1][1]*psx - K[0][1]*psy)/d2;
        float v1  = (-K[1][0]*psx + K[0][0]*psy)/d2;
        float mult = 0.1f*(v0+v1);

        float* cb = g_cb + b*24;
        for (int r=0;r<3;r++) for (int c=0;c<3;c++) cb[r*3+c]=ext[b*16+r*4+c];
        for (int r=0;r<3;r++) cb[9+r]=ext[b*16+r*4+3];
        for (int r=0;r<3;r++) for (int c=0;c<3;c++) cb[12+r*3+c]=Ki[r][c];
        cb[21]=mult;
    }
}

/* ------------------------------------------------------------------ */
/* Main per-gaussian kernel, feat fused; means/cov direct to gmem.    */
__global__ void __launch_bounds__(GPB)
gauss_kernel(const float* __restrict__ coords, const float* __restrict__ depths,
             const float* __restrict__ opac,   const float* __restrict__ raw,
             const float* __restrict__ gf,     float* __restrict__ out){
    extern __shared__ float sm[];
    float* s_in = sm;                  /* GPB*83 (odd stride, conflict-free) */
    float* s_ft = s_in + GPB*83;       /* NHW*FTS feat tile [hw][c]          */
    float* s_D  = s_ft + NHW*FTS;      /* 165 (mask folded in)               */
    float* s_cb = s_D  + 165;          /* 24                                 */

    const int tid  = threadIdx.x;
    const int g0   = blockIdx.x*GPB;
    const int b    = g0/NGB;
    const int idx0 = g0 - b*NGB;
    const int hw0  = idx0/3;

    {
        const float MSK[5] = {1.0f, 0.025f, 0.00625f, 0.0015625f, 0.000390625f};
        for (int i=tid;i<165;i+=GPB){
            int l = (i>=84)?4:(i>=35)?3:(i>=10)?2:(i>=1)?1:0;
            s_D[i] = g_D[b*165+i]*MSK[l];
        }
    }
    if (tid < 24) s_cb[tid] = g_cb[b*24+tid];

    /* stage feat tile: [hw][c], coalesced gmem reads */
    {
        const float* gfb = gf + (size_t)b*CCH*HWD;
        #pragma unroll 4
        for (int i=tid; i<CCH*NHW; i+=GPB){
            int c = i/NHW, j = i - c*NHW;
            int hwrow = hw0 + j;
            float v = (hwrow < HWD) ? gfb[(size_t)c*HWD + hwrow] : 0.f;
            s_ft[j*FTS + c] = v;
        }
    }

    /* stage raw_gaussians: coalesced float4 loads -> padded rows */
    {
        const float4* src = reinterpret_cast<const float4*>(raw + (size_t)g0*82);
        #pragma unroll 4
        for (int i=tid; i<GPB*82/4; i+=GPB){
            float4 v = src[i];
            int lin = i*4;
            float vv[4] = {v.x, v.y, v.z, v.w};
            #pragma unroll
            for (int w=0; w<4; w++){
                int t = (lin+w)/82;
                int j = (lin+w) - t*82;
                s_in[t*83 + j] = vv[w];
            }
        }
    }
    __syncthreads();

    const int g = g0 + tid;
    float* in = s_in + tid*83;
    const float  depth = depths[g];
    const float2 uv = reinterpret_cast<const float2*>(coords)[g];
    out[OFF_OPA + g] = opac[g];

    /* scales */
    const float mult = s_cb[21];
    float sc[3];
    #pragma unroll
    for (int i=0;i<3;i++){
        float x = in[i];
        float sig = 1.0f/(1.0f+expf(-x));
        sc[i] = (0.5f + 14.5f*sig) * depth * mult;
    }
    /* quaternion -> rotation */
    float q0=in[3], q1=in[4], q2=in[5], q3=in[6];
    float nq = sqrtf(q0*q0+q1*q1+q2*q2+q3*q3);
    float invq = 1.0f/(nq + 1e-8f);
    q0*=invq; q1*=invq; q2*=invq; q3*=invq;
    float ss = 2.0f/(q0*q0+q1*q1+q2*q2+q3*q3);
    const float r=q0, ii=q1, jj=q2, kk=q3;
    float R00=1.f-ss*(jj*jj+kk*kk), R01=ss*(ii*jj-kk*r), R02=ss*(ii*kk+jj*r);
    float R10=ss*(ii*jj+kk*r), R11=1.f-ss*(ii*ii+kk*kk), R12=ss*(jj*kk-ii*r);
    float R20=ss*(ii*kk-jj*r), R21=ss*(jj*kk+ii*r), R22=1.f-ss*(ii*ii+jj*jj);
    float v0=sc[0]*sc[0], v1=sc[1]*sc[1], v2=sc[2]*sc[2];

    /* means: direct gmem write */
    {
        float dx = s_cb[12]*uv.x + s_cb[13]*uv.y + s_cb[14];
        float dy = s_cb[15]*uv.x + s_cb[16]*uv.y + s_cb[17];
        float dz = s_cb[18]*uv.x + s_cb[19]*uv.y + s_cb[20];
        float dn = 1.0f/sqrtf(dx*dx+dy*dy+dz*dz);
        dx*=dn; dy*=dn; dz*=dn;
        float wx = s_cb[0]*dx + s_cb[1]*dy + s_cb[2]*dz;
        float wy = s_cb[3]*dx + s_cb[4]*dy + s_cb[5]*dz;
        float wz = s_cb[6]*dx + s_cb[7]*dy + s_cb[8]*dz;
        float* mo = out + OFF_MEANS + (size_t)g*3;
        mo[0] = s_cb[9]  + wx*depth;
        mo[1] = s_cb[10] + wy*depth;
        mo[2] = s_cb[11] + wz*depth;
    }
    /* covariance: direct gmem write */
    {
        float c00=R00*R00*v0+R01*R01*v1+R02*R02*v2;
        float c01=R00*R10*v0+R01*R11*v1+R02*R12*v2;
        float c02=R00*R20*v0+R01*R21*v1+R02*R22*v2;
        float c11=R10*R10*v0+R11*R11*v1+R12*R12*v2;
        float c12=R10*R20*v0+R11*R21*v1+R12*R22*v2;
        float c22=R20*R20*v0+R21*R21*v1+R22*R22*v2;
        float* co = out + OFF_COV + (size_t)g*9;
        co[0]=c00; co[1]=c01; co[2]=c02;
        co[3]=c01; co[4]=c11; co[5]=c12;
        co[6]=c02; co[7]=c12; co[8]=c22;
    }

    /* SH rotation IN PLACE, 3 channels fused, mask folded into s_D */
    {
        float* shp = in + 7;
        const float d0 = s_D[0];
        shp[0]*=d0; shp[25]*=d0; shp[50]*=d0;
        const int LOFFc[5] = {0,1,10,35,84};
        #pragma unroll
        for (int l=1;l<5;l++){
            const int n = 2*l+1, off = l*l;
            const float* D = s_D + LOFFc[l];
            float t0[9], t1[9], t2[9];
            #pragma unroll
            for (int j=0;j<n;j++){
                t0[j]=shp[off+j]; t1[j]=shp[25+off+j]; t2[j]=shp[50+off+j];
            }
            #pragma unroll
            for (int i=0;i<n;i++){
                float a0=0.f, a1=0.f, a2=0.f;
                #pragma unroll
                for (int j=0;j<n;j++){
                    float d = D[i*n+j];
                    a0 += d*t0[j]; a1 += d*t1[j]; a2 += d*t2[j];
                }
                shp[off+i]=a0; shp[25+off+i]=a1; shp[50+off+i]=a2;
            }
        }
    }
    /* stash scales + normalized quat into freed slots */
    in[0]=sc[0]; in[1]=sc[1]; in[2]=sc[2];
    in[3]=q0; in[4]=q1; in[5]=q2; in[6]=q3;
    __syncthreads();

    /* coalesced float4 flush */
    {
        /* SH */
        float4* d4 = (float4*)(out + OFF_SH + (size_t)g0*75);
        #pragma unroll 4
        for (int i=tid; i<GPB*75/4; i+=GPB){
            int lin = i*4; float vv[4];
            #pragma unroll
            for (int w=0;w<4;w++){
                int idx=lin+w, t=idx/75, j=idx-t*75;
                vv[w] = s_in[t*83+7+j];
            }
            d4[i] = make_float4(vv[0],vv[1],vv[2],vv[3]);
        }
        /* features: LDS128 from [hw][c] tile */
        d4 = (float4*)(out + OFF_FEAT + (size_t)g0*64);
        #pragma unroll 4
        for (int i=tid; i<GPB*64/4; i+=GPB){
            int lin = i*4;
            int gl  = lin>>6;
            int c0  = lin & 63;
            int hwl = (idx0+gl)/3 - hw0;
            d4[i] = *reinterpret_cast<const float4*>(&s_ft[hwl*FTS + c0]);
        }
        /* scales */
        d4 = (float4*)(out + OFF_SCL + (size_t)g0*3);
        for (int i=tid; i<GPB*3/4; i+=GPB){
            int lin=i*4; float vv[4];
            #pragma unroll
            for (int w=0;w<4;w++){
                int idx=lin+w, t=idx/3, j=idx-t*3;
                vv[w] = s_in[t*83+j];
            }
            d4[i] = make_float4(vv[0],vv[1],vv[2],vv[3]);
        }
        /* rotations */
        d4 = (float4*)(out + OFF_ROT + (size_t)g0*4);
        for (int i=tid; i<GPB; i+=GPB){
            const float* rt = s_in + i*83 + 3;
            d4[i] = make_float4(rt[0],rt[1],rt[2],rt[3]);
        }
    }
}

/* ------------------------------------------------------------------ */
extern "C" void kernel_launch(void* const* d_in, const int* in_sizes, int n_in,
                              void* d_out, int out_size){
    const float* ext    = (const float*)d_in[0];
    const float* intr   = (const float*)d_in[1];
    const float* coords = (const float*)d_in[2];
    const float* depths = (const float*)d_in[3];
    const float* opac   = (const float*)d_in[4];
    const float* raw    = (const float*)d_in[5];
    const float* gf     = (const float*)d_in[6];
    const void*  ph     = (n_in > 7) ? d_in[7] : nullptr;
    const void*  pw     = (n_in > 8) ? d_in[8] : nullptr;
    float* out = (float*)d_out;

    setup_kernel<<<BB*5, 32>>>(ext, intr, ph, pw);

    size_t smem = (size_t)(GPB*83 + NHW*FTS + 165 + 24)*sizeof(float);
    cudaFuncSetAttribute(gauss_kernel, cudaFuncAttributeMaxDynamicSharedMemorySize, (int)smem);
    gauss_kernel<<<NG/GPB, GPB, smem>>>(coords, depths, opac, raw, gf, out);
}